// round 4
// baseline (speedup 1.0000x reference)
#include <cuda_runtime.h>
#include <cuda_bf16.h>
#include <cstdint>

#define H_DIM 2048
#define B_DIM 4096
#define A_DIM 5
#define T_STEPS 10
#define WC_SCALE 128.0f
#define WC_INV (1.0f / 128.0f)

// ---------------- device scratch (no allocation allowed) ----------------
__device__ __align__(256) uint8_t g_x8[B_DIM * H_DIM];        // x in e4m3      ( 8 MB)
__device__ __align__(256) __nv_bfloat16 g_Winb[H_DIM * H_DIM];  // W_in bf16    ( 8 MB)
__device__ __align__(256) __nv_bfloat16 g_WsnnT[H_DIM * H_DIM]; // W_snn^T bf16 ( 8 MB)
__device__ __align__(256) uint8_t g_WcT8[H_DIM * H_DIM];      // 128*(Wc)^T e4m3 (4 MB)
__device__ __align__(256) __nv_bfloat16 g_rate[B_DIM * H_DIM];  // LIF rates   (16 MB)
__device__ float g_bp[H_DIM];
__device__ float g_bp_part[64][H_DIM];

// ---------------- helpers ----------------
__device__ __forceinline__ uint32_t smem_u32(const void* p) {
    return (uint32_t)__cvta_generic_to_shared(p);
}
__device__ __forceinline__ void cp_async16(uint32_t dst, const void* src) {
    asm volatile("cp.async.cg.shared.global [%0], [%1], 16;" :: "r"(dst), "l"(src));
}
__device__ __forceinline__ void cp_commit() {
    asm volatile("cp.async.commit_group;");
}
template <int N>
__device__ __forceinline__ void cp_wait() {
    asm volatile("cp.async.wait_group %0;" :: "n"(N));
}
__device__ __forceinline__ void ldm_x4(uint32_t* r, uint32_t addr) {
    asm volatile("ldmatrix.sync.aligned.m8n8.x4.shared.b16 {%0,%1,%2,%3}, [%4];"
                 : "=r"(r[0]), "=r"(r[1]), "=r"(r[2]), "=r"(r[3]) : "r"(addr));
}
__device__ __forceinline__ void mma_bf16(float* c, const uint32_t* a, const uint32_t* b) {
    asm volatile(
        "mma.sync.aligned.m16n8k16.row.col.f32.bf16.bf16.f32 "
        "{%0,%1,%2,%3}, {%4,%5,%6,%7}, {%8,%9}, {%0,%1,%2,%3};"
        : "+f"(c[0]), "+f"(c[1]), "+f"(c[2]), "+f"(c[3])
        : "r"(a[0]), "r"(a[1]), "r"(a[2]), "r"(a[3]), "r"(b[0]), "r"(b[1]));
}
__device__ __forceinline__ void mma_fp8(float* c, const uint32_t* a, const uint32_t* b) {
    asm volatile(
        "mma.sync.aligned.m16n8k32.row.col.f32.e4m3.e4m3.f32 "
        "{%0,%1,%2,%3}, {%4,%5,%6,%7}, {%8,%9}, {%0,%1,%2,%3};"
        : "+f"(c[0]), "+f"(c[1]), "+f"(c[2]), "+f"(c[3])
        : "r"(a[0]), "r"(a[1]), "r"(a[2]), "r"(a[3]), "r"(b[0]), "r"(b[1]));
}
// pack: low byte = e4m3(lo), high byte = e4m3(hi)
__device__ __forceinline__ unsigned short fp8x2(float hi, float lo) {
    unsigned short u;
    asm("cvt.rn.satfinite.e4m3x2.f32 %0, %1, %2;" : "=h"(u) : "f"(hi), "f"(lo));
    return u;
}

__device__ __forceinline__ float lif_rate(float c) {
    float v = 0.f, cnt = 0.f;
#pragma unroll
    for (int t = 0; t < T_STEPS; t++) {
        v = v + (c - v) * 0.5f;
        if (v >= 1.0f) { cnt += 1.0f; v = 0.0f; }
    }
    return cnt * 0.1f;
}

#define BKU 32    // K tile in 2-byte units
#define SPAD 40   // padded row stride in 2-byte units (80 B)

// ---------------- bf16 HMMA GEMM1: D[M,N] = A[M,K]@B[N,K]^T, store e4m3(D*128)
__global__ void __launch_bounds__(256, 2) gemm_bf16_to_fp8(
    const __nv_bfloat16* __restrict__ A, const __nv_bfloat16* __restrict__ B,
    uint8_t* __restrict__ C, int N, int K)
{
    __shared__ __nv_bfloat16 As[2][128][SPAD];
    __shared__ __nv_bfloat16 Bs[2][128][SPAD];

    const int tid = threadIdx.x;
    const int wid = tid >> 5;
    const int lane = tid & 31;
    const int bm = blockIdx.y * 128;
    const int bn = blockIdx.x * 128;
    const int wm = (wid >> 1) * 32;
    const int wn = (wid & 1) * 64;

    float acc[2][8][4];
#pragma unroll
    for (int mi = 0; mi < 2; mi++)
#pragma unroll
        for (int ni = 0; ni < 8; ni++)
#pragma unroll
            for (int j = 0; j < 4; j++) acc[mi][ni][j] = 0.f;

    auto stage = [&](int k0, int b) {
#pragma unroll
        for (int i = 0; i < 2; i++) {
            int id = tid + i * 256;
            int r = id >> 2, c = (id & 3) * 8;
            cp_async16(smem_u32(&As[b][r][c]), A + (size_t)(bm + r) * K + k0 + c);
            cp_async16(smem_u32(&Bs[b][r][c]), B + (size_t)(bn + r) * K + k0 + c);
        }
        cp_commit();
    };

    const int NS = K / BKU;
    stage(0, 0);
    for (int s = 0; s < NS; s++) {
        if (s + 1 < NS) { stage((s + 1) * BKU, (s + 1) & 1); cp_wait<1>(); }
        else            { cp_wait<0>(); }
        __syncthreads();
        const int b = s & 1;
#pragma unroll
        for (int ks = 0; ks < 2; ks++) {
            uint32_t af[2][4];
#pragma unroll
            for (int mi = 0; mi < 2; mi++)
                ldm_x4(af[mi], smem_u32(&As[b][wm + mi * 16 + (lane & 15)]
                                           [ks * 16 + (lane >> 4) * 8]));
            uint32_t bf[4][4];
#pragma unroll
            for (int np = 0; np < 4; np++) {
                int rrow = wn + np * 16 + (lane & 7) + ((lane >> 4) << 3);
                int rcol = ks * 16 + (((lane >> 3) & 1) << 3);
                ldm_x4(bf[np], smem_u32(&Bs[b][rrow][rcol]));
            }
#pragma unroll
            for (int mi = 0; mi < 2; mi++)
#pragma unroll
                for (int ni = 0; ni < 8; ni++)
                    mma_bf16(acc[mi][ni], af[mi], &bf[ni >> 1][(ni & 1) * 2]);
        }
        __syncthreads();
    }

    const int gr = lane >> 2;
    const int gc = (lane & 3) * 2;
#pragma unroll
    for (int mi = 0; mi < 2; mi++) {
#pragma unroll
        for (int ni = 0; ni < 8; ni++) {
            int col = bn + wn + ni * 8 + gc;
            int row0 = bm + wm + mi * 16 + gr;
            unsigned short lo = fp8x2(acc[mi][ni][1] * WC_SCALE, acc[mi][ni][0] * WC_SCALE);
            unsigned short hi = fp8x2(acc[mi][ni][3] * WC_SCALE, acc[mi][ni][2] * WC_SCALE);
            *(unsigned short*)&C[(size_t)row0 * N + col] = lo;
            *(unsigned short*)&C[(size_t)(row0 + 8) * N + col] = hi;
        }
    }
}

// ---------------- fp8 GEMM2: D = A[M,Kb]@B[N,Kb]^T (e4m3), rate = lif(D/128 + bias)
__global__ void __launch_bounds__(256, 2) gemm_fp8_lif(
    const uint8_t* __restrict__ A, const uint8_t* __restrict__ B,
    __nv_bfloat16* __restrict__ C, const float* __restrict__ bias,
    int N, int Kb)   // Kb = K in bytes (2048)
{
    __shared__ __nv_bfloat16 As[2][128][SPAD];   // 2-byte units (fp8 pairs)
    __shared__ __nv_bfloat16 Bs[2][128][SPAD];

    const int tid = threadIdx.x;
    const int wid = tid >> 5;
    const int lane = tid & 31;
    const int bm = blockIdx.y * 128;
    const int bn = blockIdx.x * 128;
    const int wm = (wid >> 1) * 32;
    const int wn = (wid & 1) * 64;

    float acc[2][8][4];
#pragma unroll
    for (int mi = 0; mi < 2; mi++)
#pragma unroll
        for (int ni = 0; ni < 8; ni++)
#pragma unroll
            for (int j = 0; j < 4; j++) acc[mi][ni][j] = 0.f;

    auto stage = [&](int k0b, int b) {   // k0b: byte offset in K
#pragma unroll
        for (int i = 0; i < 2; i++) {
            int id = tid + i * 256;
            int r = id >> 2, c = (id & 3) * 8;       // c: 2-byte-unit col
            cp_async16(smem_u32(&As[b][r][c]), A + (size_t)(bm + r) * Kb + k0b + c * 2);
            cp_async16(smem_u32(&Bs[b][r][c]), B + (size_t)(bn + r) * Kb + k0b + c * 2);
        }
        cp_commit();
    };

    const int NS = Kb / (BKU * 2);   // 32 slabs of 64 fp8-K
    stage(0, 0);
    for (int s = 0; s < NS; s++) {
        if (s + 1 < NS) { stage((s + 1) * BKU * 2, (s + 1) & 1); cp_wait<1>(); }
        else            { cp_wait<0>(); }
        __syncthreads();
        const int b = s & 1;
#pragma unroll
        for (int ks = 0; ks < 2; ks++) {             // each ks = k32 fp8
            uint32_t af[2][4];
#pragma unroll
            for (int mi = 0; mi < 2; mi++)
                ldm_x4(af[mi], smem_u32(&As[b][wm + mi * 16 + (lane & 15)]
                                           [ks * 16 + (lane >> 4) * 8]));
            uint32_t bf[4][4];
#pragma unroll
            for (int np = 0; np < 4; np++) {
                int rrow = wn + np * 16 + (lane & 7) + ((lane >> 4) << 3);
                int rcol = ks * 16 + (((lane >> 3) & 1) << 3);
                ldm_x4(bf[np], smem_u32(&Bs[b][rrow][rcol]));
            }
#pragma unroll
            for (int mi = 0; mi < 2; mi++)
#pragma unroll
                for (int ni = 0; ni < 8; ni++)
                    mma_fp8(acc[mi][ni], af[mi], &bf[ni >> 1][(ni & 1) * 2]);
        }
        __syncthreads();
    }

    const int gr = lane >> 2;
    const int gc = (lane & 3) * 2;
#pragma unroll
    for (int mi = 0; mi < 2; mi++) {
#pragma unroll
        for (int ni = 0; ni < 8; ni++) {
            int col = bn + wn + ni * 8 + gc;
            int row0 = bm + wm + mi * 16 + gr;
            float b0 = bias[col], b1 = bias[col + 1];
            __nv_bfloat162 lo = __floats2bfloat162_rn(
                lif_rate(acc[mi][ni][0] * WC_INV + b0),
                lif_rate(acc[mi][ni][1] * WC_INV + b1));
            __nv_bfloat162 hi = __floats2bfloat162_rn(
                lif_rate(acc[mi][ni][2] * WC_INV + b0),
                lif_rate(acc[mi][ni][3] * WC_INV + b1));
            *(__nv_bfloat162*)&C[(size_t)row0 * N + col] = lo;
            *(__nv_bfloat162*)&C[(size_t)(row0 + 8) * N + col] = hi;
        }
    }
}

// ---------------- conversion kernels ----------------
// x (f32) -> e4m3, 4 elements/thread
__global__ void conv_fp8_kernel(const float4* __restrict__ in, unsigned int* __restrict__ out,
                                int n4) {
    int i = blockIdx.x * 256 + threadIdx.x;
    if (i < n4) {
        float4 v = in[i];
        unsigned int lo = fp8x2(v.y, v.x);
        unsigned int hi = fp8x2(v.w, v.z);
        out[i] = lo | (hi << 16);
    }
}

__global__ void conv_bf16_kernel(const float4* __restrict__ in, uint2* __restrict__ out, int n4) {
    int i = blockIdx.x * 256 + threadIdx.x;
    if (i < n4) {
        float4 v = in[i];
        __nv_bfloat162 lo = __floats2bfloat162_rn(v.x, v.y);
        __nv_bfloat162 hi = __floats2bfloat162_rn(v.z, v.w);
        uint2 o;
        o.x = *reinterpret_cast<unsigned int*>(&lo);
        o.y = *reinterpret_cast<unsigned int*>(&hi);
        out[i] = o;
    }
}

// out[j,m] = bf16(in[m,j]); also bias partials: g_bp_part[by][j] = sum_mi b_in[m0+mi]*in[m0+mi][j]
__global__ void convT_bf16_bias_kernel(const float* __restrict__ in,
                                       const float* __restrict__ b_in,
                                       __nv_bfloat16* __restrict__ out) {
    __shared__ float t[32][33];
    int j0 = blockIdx.x * 32, m0 = blockIdx.y * 32;
    int tx = threadIdx.x, ty = threadIdx.y;   // 32 x 8
#pragma unroll
    for (int i = 0; i < 4; i++)
        t[ty + i * 8][tx] = in[(size_t)(m0 + ty + i * 8) * H_DIM + j0 + tx];
    __syncthreads();
#pragma unroll
    for (int i = 0; i < 4; i++)
        out[(size_t)(j0 + ty + i * 8) * H_DIM + m0 + tx] = __float2bfloat16(t[tx][ty + i * 8]);
    if (ty == 0) {
        float acc = 0.f;
#pragma unroll 8
        for (int mi = 0; mi < 32; mi++)
            acc = fmaf(b_in[m0 + mi], t[mi][tx], acc);
        g_bp_part[blockIdx.y][j0 + tx] = acc;
    }
}

__global__ void bp_reduce_kernel(const float* __restrict__ b_snn) {
    int j = blockIdx.x * 256 + threadIdx.x;
    float acc = b_snn[j];
#pragma unroll
    for (int p = 0; p < 64; p++) acc += g_bp_part[p][j];
    g_bp[j] = acc;
}

// ---------------- output head (rate in bf16) ----------------
__global__ void head_kernel(const __nv_bfloat16* __restrict__ rate,
                            const float* __restrict__ W_out,
                            const float* __restrict__ b_out,
                            float* __restrict__ out) {
    __shared__ float sW[H_DIM * A_DIM];
    for (int i = threadIdx.x; i < H_DIM * A_DIM; i += blockDim.x)
        sW[i] = W_out[i];
    __syncthreads();

    int warp = threadIdx.x >> 5;
    int lane = threadIdx.x & 31;
    int row = blockIdx.x * 8 + warp;
    const __nv_bfloat16* r = rate + (size_t)row * H_DIM;

    float acc[A_DIM];
#pragma unroll
    for (int a = 0; a < A_DIM; a++) acc[a] = 0.f;
    for (int k = lane; k < H_DIM; k += 32) {
        float rv = __bfloat162float(r[k]);
#pragma unroll
        for (int a = 0; a < A_DIM; a++)
            acc[a] = fmaf(rv, sW[k * A_DIM + a], acc[a]);
    }
#pragma unroll
    for (int a = 0; a < A_DIM; a++) {
#pragma unroll
        for (int off = 16; off; off >>= 1)
            acc[a] += __shfl_xor_sync(0xffffffffu, acc[a], off);
    }
    if (lane < A_DIM) {
        float pre = acc[lane] + b_out[lane];
        float v = pre * 0.5f;
        out[(size_t)row * A_DIM + lane] = (v - 1.0f >= 0.f) ? 1.f : 0.f;
    }
}

// ---------------- launch ----------------
extern "C" void kernel_launch(void* const* d_in, const int* in_sizes, int n_in,
                              void* d_out, int out_size) {
    const float* x     = (const float*)d_in[0];
    const float* W_in  = (const float*)d_in[1];
    const float* b_in  = (const float*)d_in[2];
    const float* W_snn = (const float*)d_in[3];
    const float* b_snn = (const float*)d_in[4];
    const float* W_out = (const float*)d_in[5];
    const float* b_out = (const float*)d_in[6];
    float* out = (float*)d_out;

    uint8_t *x8, *WcT8;
    __nv_bfloat16 *Winb, *WsnnT, *rate;
    float *bp;
    cudaGetSymbolAddress((void**)&x8,    g_x8);
    cudaGetSymbolAddress((void**)&Winb,  g_Winb);
    cudaGetSymbolAddress((void**)&WsnnT, g_WsnnT);
    cudaGetSymbolAddress((void**)&WcT8,  g_WcT8);
    cudaGetSymbolAddress((void**)&rate,  g_rate);
    cudaGetSymbolAddress((void**)&bp,    g_bp);

    // conversions
    conv_fp8_kernel<<<(B_DIM * H_DIM / 4 + 255) / 256, 256>>>(
        (const float4*)x, (unsigned int*)x8, B_DIM * H_DIM / 4);
    conv_bf16_kernel<<<(H_DIM * H_DIM / 4 + 255) / 256, 256>>>(
        (const float4*)W_in, (uint2*)Winb, H_DIM * H_DIM / 4);
    convT_bf16_bias_kernel<<<dim3(H_DIM / 32, H_DIM / 32), dim3(32, 8)>>>(W_snn, b_in, WsnnT);
    bp_reduce_kernel<<<H_DIM / 256, 256>>>(b_snn);

    // GEMM1: WcT8[j,i] = e4m3(128 * sum_m WsnnT[j,m] * Winb[i,m])
    gemm_bf16_to_fp8<<<dim3(H_DIM / 128, H_DIM / 128), 256>>>(
        WsnnT, Winb, WcT8, H_DIM, H_DIM);

    // GEMM2: rate[b,n] = bf16(lif(sum_k x8[b,k]*WcT8[n,k]/128 + bp[n]))
    gemm_fp8_lif<<<dim3(H_DIM / 128, B_DIM / 128), 256>>>(
        x8, WcT8, rate, bp, H_DIM, H_DIM);

    // head
    head_kernel<<<B_DIM / 8, 256>>>(rate, W_out, b_out, out);
}

// round 5
// speedup vs baseline: 1.1521x; 1.1521x over previous
#include <cuda_runtime.h>
#include <cuda_bf16.h>
#include <cstdint>

#define H_DIM 2048
#define B_DIM 4096
#define A_DIM 5
#define T_STEPS 10

// ---------------- device scratch (no allocation allowed) ----------------
__device__ __align__(256) __nv_bfloat16 g_xb[B_DIM * H_DIM];    // x bf16       (16 MB)
__device__ __align__(256) __nv_bfloat16 g_Winb[H_DIM * H_DIM];  // W_in bf16    ( 8 MB)
__device__ __align__(256) __nv_bfloat16 g_WsnnT[H_DIM * H_DIM]; // W_snn^T bf16 ( 8 MB)
__device__ __align__(256) __nv_bfloat16 g_WcT[H_DIM * H_DIM];   // Wc^T bf16    ( 8 MB)
__device__ float g_pre[B_DIM * A_DIM];                          // head pre-activation
__device__ float g_bp[H_DIM];
__device__ float g_bp_part[64][H_DIM];

// ---------------- helpers ----------------
__device__ __forceinline__ uint32_t smem_u32(const void* p) {
    return (uint32_t)__cvta_generic_to_shared(p);
}
__device__ __forceinline__ void cp_async16(uint32_t dst, const void* src) {
    asm volatile("cp.async.cg.shared.global [%0], [%1], 16;" :: "r"(dst), "l"(src));
}
__device__ __forceinline__ void cp_commit() {
    asm volatile("cp.async.commit_group;");
}
template <int N>
__device__ __forceinline__ void cp_wait() {
    asm volatile("cp.async.wait_group %0;" :: "n"(N));
}
__device__ __forceinline__ void ldm_x4(uint32_t* r, uint32_t addr) {
    asm volatile("ldmatrix.sync.aligned.m8n8.x4.shared.b16 {%0,%1,%2,%3}, [%4];"
                 : "=r"(r[0]), "=r"(r[1]), "=r"(r[2]), "=r"(r[3]) : "r"(addr));
}
__device__ __forceinline__ void mma_bf16(float* c, const uint32_t* a, const uint32_t* b) {
    asm volatile(
        "mma.sync.aligned.m16n8k16.row.col.f32.bf16.bf16.f32 "
        "{%0,%1,%2,%3}, {%4,%5,%6,%7}, {%8,%9}, {%0,%1,%2,%3};"
        : "+f"(c[0]), "+f"(c[1]), "+f"(c[2]), "+f"(c[3])
        : "r"(a[0]), "r"(a[1]), "r"(a[2]), "r"(a[3]), "r"(b[0]), "r"(b[1]));
}

__device__ __forceinline__ float lif_rate(float c) {
    float v = 0.f, cnt = 0.f;
#pragma unroll
    for (int t = 0; t < T_STEPS; t++) {
        v = v + (c - v) * 0.5f;
        if (v >= 1.0f) { cnt += 1.0f; v = 0.0f; }
    }
    return cnt * 0.1f;
}

#define BKU 64    // K tile in bf16 units (128 B rows)
#define SPAD 72   // padded row stride (144 B): conflict-free ldmatrix
#define SM_ELE (2 * 128 * SPAD)                 // per array
#define GEMM_SMEM (2 * SM_ELE * (int)sizeof(__nv_bfloat16))   // 73728 B

// ---------------- bf16 HMMA GEMM: D[M,N] = A[M,K] @ B[N,K]^T
// EPI=0: store bf16 D.  EPI=1: LIF + head-fused: atomicAdd rate@Wout into pre.
template <int EPI>
__global__ void __launch_bounds__(256, 2) gemm_mma(
    const __nv_bfloat16* __restrict__ A, const __nv_bfloat16* __restrict__ B,
    __nv_bfloat16* __restrict__ Cv, const float* __restrict__ bias,
    const float* __restrict__ Wout, float* __restrict__ pre, int N, int K)
{
    extern __shared__ __nv_bfloat16 sm[];
    __nv_bfloat16 (*As)[128][SPAD] = (__nv_bfloat16 (*)[128][SPAD])sm;
    __nv_bfloat16 (*Bs)[128][SPAD] = (__nv_bfloat16 (*)[128][SPAD])(sm + SM_ELE);

    const int tid = threadIdx.x;
    const int wid = tid >> 5;
    const int lane = tid & 31;
    const int bm = blockIdx.y * 128;
    const int bn = blockIdx.x * 128;
    const int wm = (wid >> 1) * 32;
    const int wn = (wid & 1) * 64;

    float acc[2][8][4];
#pragma unroll
    for (int mi = 0; mi < 2; mi++)
#pragma unroll
        for (int ni = 0; ni < 8; ni++)
#pragma unroll
            for (int j = 0; j < 4; j++) acc[mi][ni][j] = 0.f;

    auto stage = [&](int k0, int b) {
#pragma unroll
        for (int i = 0; i < 4; i++) {
            int id = tid + i * 256;             // 0..1023
            int r = id >> 3, c = (id & 7) * 8;  // 8 chunks of 8 units per row
            cp_async16(smem_u32(&As[b][r][c]), A + (size_t)(bm + r) * K + k0 + c);
            cp_async16(smem_u32(&Bs[b][r][c]), B + (size_t)(bn + r) * K + k0 + c);
        }
        cp_commit();
    };

    const int NS = K / BKU;    // 32
    stage(0, 0);
    for (int s = 0; s < NS; s++) {
        if (s + 1 < NS) { stage((s + 1) * BKU, (s + 1) & 1); cp_wait<1>(); }
        else            { cp_wait<0>(); }
        __syncthreads();
        const int b = s & 1;
#pragma unroll
        for (int ks = 0; ks < 4; ks++) {
            uint32_t af[2][4];
#pragma unroll
            for (int mi = 0; mi < 2; mi++)
                ldm_x4(af[mi], smem_u32(&As[b][wm + mi * 16 + (lane & 15)]
                                           [ks * 16 + (lane >> 4) * 8]));
            uint32_t bf[4][4];
#pragma unroll
            for (int np = 0; np < 4; np++) {
                int rrow = wn + np * 16 + (lane & 7) + ((lane >> 4) << 3);
                int rcol = ks * 16 + (((lane >> 3) & 1) << 3);
                ldm_x4(bf[np], smem_u32(&Bs[b][rrow][rcol]));
            }
#pragma unroll
            for (int mi = 0; mi < 2; mi++)
#pragma unroll
                for (int ni = 0; ni < 8; ni++)
                    mma_bf16(acc[mi][ni], af[mi], &bf[ni >> 1][(ni & 1) * 2]);
        }
        __syncthreads();
    }

    const int gr = lane >> 2;         // 0..7
    const int gc = (lane & 3) * 2;    // 0,2,4,6

    if (EPI == 0) {
#pragma unroll
        for (int mi = 0; mi < 2; mi++) {
#pragma unroll
            for (int ni = 0; ni < 8; ni++) {
                int col = bn + wn + ni * 8 + gc;
                int row0 = bm + wm + mi * 16 + gr;
                __nv_bfloat162 lo = __floats2bfloat162_rn(acc[mi][ni][0], acc[mi][ni][1]);
                __nv_bfloat162 hi = __floats2bfloat162_rn(acc[mi][ni][2], acc[mi][ni][3]);
                *(__nv_bfloat162*)&Cv[(size_t)row0 * N + col] = lo;
                *(__nv_bfloat162*)&Cv[(size_t)(row0 + 8) * N + col] = hi;
            }
        }
    } else {
        // stage W_out tile [128][5] and bias tile [128] into smem (reuse As)
        float* sW = (float*)sm;
        float* sbp = sW + 128 * A_DIM;
        for (int i = tid; i < 128 * A_DIM; i += 256) {
            int c = i / A_DIM, a = i % A_DIM;
            sW[i] = Wout[(size_t)(bn + c) * A_DIM + a];
        }
        for (int i = tid; i < 128; i += 256) sbp[i] = bias[bn + i];
        __syncthreads();

#pragma unroll
        for (int mi = 0; mi < 2; mi++) {
#pragma unroll
            for (int h = 0; h < 2; h++) {
                float p[A_DIM];
#pragma unroll
                for (int a = 0; a < A_DIM; a++) p[a] = 0.f;
#pragma unroll
                for (int ni = 0; ni < 8; ni++) {
                    int cl = wn + ni * 8 + gc;
                    float v0 = lif_rate(acc[mi][ni][2 * h + 0] + sbp[cl]);
                    float v1 = lif_rate(acc[mi][ni][2 * h + 1] + sbp[cl + 1]);
#pragma unroll
                    for (int a = 0; a < A_DIM; a++)
                        p[a] = fmaf(v0, sW[cl * A_DIM + a],
                                    fmaf(v1, sW[(cl + 1) * A_DIM + a], p[a]));
                }
#pragma unroll
                for (int a = 0; a < A_DIM; a++) {
                    p[a] += __shfl_xor_sync(0xffffffffu, p[a], 1);
                    p[a] += __shfl_xor_sync(0xffffffffu, p[a], 2);
                }
                if ((lane & 3) == 0) {
                    int row = bm + wm + mi * 16 + h * 8 + gr;
#pragma unroll
                    for (int a = 0; a < A_DIM; a++)
                        atomicAdd(&pre[(size_t)row * A_DIM + a], p[a]);
                }
            }
        }
    }
}

// ---------------- conversion kernels ----------------
__global__ void conv_bf16_kernel(const float4* __restrict__ in, uint2* __restrict__ out, int n4) {
    int i = blockIdx.x * 256 + threadIdx.x;
    if (i < n4) {
        float4 v = in[i];
        __nv_bfloat162 lo = __floats2bfloat162_rn(v.x, v.y);
        __nv_bfloat162 hi = __floats2bfloat162_rn(v.z, v.w);
        uint2 o;
        o.x = *reinterpret_cast<unsigned int*>(&lo);
        o.y = *reinterpret_cast<unsigned int*>(&hi);
        out[i] = o;
    }
}

// out[j,m] = bf16(in[m,j]); also bias partials g_bp_part[m-blk][j]
__global__ void convT_bf16_bias_kernel(const float* __restrict__ in,
                                       const float* __restrict__ b_in,
                                       __nv_bfloat16* __restrict__ out) {
    __shared__ float t[32][33];
    int j0 = blockIdx.x * 32, m0 = blockIdx.y * 32;
    int tx = threadIdx.x, ty = threadIdx.y;   // 32 x 8
#pragma unroll
    for (int i = 0; i < 4; i++)
        t[ty + i * 8][tx] = in[(size_t)(m0 + ty + i * 8) * H_DIM + j0 + tx];
    __syncthreads();
#pragma unroll
    for (int i = 0; i < 4; i++)
        out[(size_t)(j0 + ty + i * 8) * H_DIM + m0 + tx] = __float2bfloat16(t[tx][ty + i * 8]);
    if (ty == 0) {
        float acc = 0.f;
#pragma unroll 8
        for (int mi = 0; mi < 32; mi++)
            acc = fmaf(b_in[m0 + mi], t[mi][tx], acc);
        g_bp_part[blockIdx.y][j0 + tx] = acc;
    }
}

__global__ void bp_reduce_kernel(const float* __restrict__ b_snn) {
    int j = blockIdx.x * 256 + threadIdx.x;
    float acc = b_snn[j];
#pragma unroll
    for (int p = 0; p < 64; p++) acc += g_bp_part[p][j];
    g_bp[j] = acc;
}

// ---------------- head finish ----------------
__global__ void zero_pre_kernel(float* __restrict__ pre) {
    int i = blockIdx.x * 256 + threadIdx.x;
    if (i < B_DIM * A_DIM) pre[i] = 0.f;
}
__global__ void head_finish_kernel(const float* __restrict__ pre,
                                   const float* __restrict__ b_out,
                                   float* __restrict__ out) {
    int i = blockIdx.x * 256 + threadIdx.x;
    if (i < B_DIM * A_DIM) {
        float v = (pre[i] + b_out[i % A_DIM]) * 0.5f;
        out[i] = (v - 1.0f >= 0.f) ? 1.f : 0.f;
    }
}

// ---------------- launch ----------------
extern "C" void kernel_launch(void* const* d_in, const int* in_sizes, int n_in,
                              void* d_out, int out_size) {
    const float* x     = (const float*)d_in[0];
    const float* W_in  = (const float*)d_in[1];
    const float* b_in  = (const float*)d_in[2];
    const float* W_snn = (const float*)d_in[3];
    const float* b_snn = (const float*)d_in[4];
    const float* W_out = (const float*)d_in[5];
    const float* b_out = (const float*)d_in[6];
    float* out = (float*)d_out;

    __nv_bfloat16 *xb, *Winb, *WsnnT, *WcT;
    float *bp, *pre;
    cudaGetSymbolAddress((void**)&xb,    g_xb);
    cudaGetSymbolAddress((void**)&Winb,  g_Winb);
    cudaGetSymbolAddress((void**)&WsnnT, g_WsnnT);
    cudaGetSymbolAddress((void**)&WcT,   g_WcT);
    cudaGetSymbolAddress((void**)&bp,    g_bp);
    cudaGetSymbolAddress((void**)&pre,   g_pre);

    cudaFuncSetAttribute(gemm_mma<0>, cudaFuncAttributeMaxDynamicSharedMemorySize, GEMM_SMEM);
    cudaFuncSetAttribute(gemm_mma<1>, cudaFuncAttributeMaxDynamicSharedMemorySize, GEMM_SMEM);

    // conversions + bias path
    conv_bf16_kernel<<<(B_DIM * H_DIM / 4 + 255) / 256, 256>>>(
        (const float4*)x, (uint2*)xb, B_DIM * H_DIM / 4);
    conv_bf16_kernel<<<(H_DIM * H_DIM / 4 + 255) / 256, 256>>>(
        (const float4*)W_in, (uint2*)Winb, H_DIM * H_DIM / 4);
    convT_bf16_bias_kernel<<<dim3(H_DIM / 32, H_DIM / 32), dim3(32, 8)>>>(W_snn, b_in, WsnnT);
    bp_reduce_kernel<<<H_DIM / 256, 256>>>(b_snn);
    zero_pre_kernel<<<(B_DIM * A_DIM + 255) / 256, 256>>>(pre);

    // GEMM1: WcT[j,i] = sum_m WsnnT[j,m] * Winb[i,m]
    gemm_mma<0><<<dim3(H_DIM / 128, H_DIM / 128), 256, GEMM_SMEM>>>(
        WsnnT, Winb, WcT, nullptr, nullptr, nullptr, H_DIM, H_DIM);

    // GEMM2 (fused LIF + head partials): pre += lif(x@WcT^T + bp) @ W_out
    gemm_mma<1><<<dim3(H_DIM / 128, B_DIM / 128), 256, GEMM_SMEM>>>(
        xb, WcT, nullptr, bp, W_out, pre, H_DIM, H_DIM);

    // finish head
    head_finish_kernel<<<(B_DIM * A_DIM + 255) / 256, 256>>>(pre, b_out, out);
}

// round 6
// speedup vs baseline: 1.1558x; 1.0031x over previous
#include <cuda_runtime.h>
#include <cuda_bf16.h>
#include <cstdint>

#define H_DIM 2048
#define B_DIM 4096
#define A_DIM 5
#define T_STEPS 10

// ---------------- device scratch (no allocation allowed) ----------------
__device__ __align__(256) __nv_bfloat16 g_xb[B_DIM * H_DIM];    // x bf16       (16 MB)
__device__ __align__(256) __nv_bfloat16 g_Winb[H_DIM * H_DIM];  // W_in bf16    ( 8 MB)
__device__ __align__(256) __nv_bfloat16 g_WsnnT[H_DIM * H_DIM]; // W_snn^T bf16 ( 8 MB)
__device__ __align__(256) __nv_bfloat16 g_WcT[H_DIM * H_DIM];   // Wc^T bf16    ( 8 MB)
__device__ float g_pre_part[16][B_DIM * A_DIM];                 // head partials (1.3 MB)
__device__ float g_bp[H_DIM];
__device__ float g_bp_part[64][H_DIM];

// ---------------- helpers ----------------
__device__ __forceinline__ uint32_t smem_u32(const void* p) {
    return (uint32_t)__cvta_generic_to_shared(p);
}
__device__ __forceinline__ void cp_async16(uint32_t dst, const void* src) {
    asm volatile("cp.async.cg.shared.global [%0], [%1], 16;" :: "r"(dst), "l"(src));
}
__device__ __forceinline__ void cp_commit() {
    asm volatile("cp.async.commit_group;");
}
template <int N>
__device__ __forceinline__ void cp_wait() {
    asm volatile("cp.async.wait_group %0;" :: "n"(N));
}
__device__ __forceinline__ void ldm_x4(uint32_t* r, uint32_t addr) {
    asm volatile("ldmatrix.sync.aligned.m8n8.x4.shared.b16 {%0,%1,%2,%3}, [%4];"
                 : "=r"(r[0]), "=r"(r[1]), "=r"(r[2]), "=r"(r[3]) : "r"(addr));
}
__device__ __forceinline__ void mma_bf16(float* c, const uint32_t* a, const uint32_t* b) {
    asm volatile(
        "mma.sync.aligned.m16n8k16.row.col.f32.bf16.bf16.f32 "
        "{%0,%1,%2,%3}, {%4,%5,%6,%7}, {%8,%9}, {%0,%1,%2,%3};"
        : "+f"(c[0]), "+f"(c[1]), "+f"(c[2]), "+f"(c[3])
        : "r"(a[0]), "r"(a[1]), "r"(a[2]), "r"(a[3]), "r"(b[0]), "r"(b[1]));
}

__device__ __forceinline__ float lif_rate(float c) {
    float v = 0.f, cnt = 0.f;
#pragma unroll
    for (int t = 0; t < T_STEPS; t++) {
        v = v + (c - v) * 0.5f;
        if (v >= 1.0f) { cnt += 1.0f; v = 0.0f; }
    }
    return cnt * 0.1f;
}

#define BK 32
#define SPAD 40                      // padded row stride (80 B), conflict-free ldmatrix
#define STG_ELE (128 * SPAD)         // elements per array per stage
#define GEMM_SMEM (3 * 2 * STG_ELE * (int)sizeof(__nv_bfloat16))   // 61440 B

// ---------------- bf16 HMMA GEMM: D[M,N] = A[M,K] @ B[N,K]^T
// EPI=0: store bf16 D.  EPI=1: LIF + head partials into pre_part[blockIdx.x].
template <int EPI>
__global__ void __launch_bounds__(256, 2) gemm_mma(
    const __nv_bfloat16* __restrict__ A, const __nv_bfloat16* __restrict__ B,
    __nv_bfloat16* __restrict__ Cv, const float* __restrict__ bias,
    const float* __restrict__ Wout, float* __restrict__ pre_part, int N, int K)
{
    extern __shared__ __nv_bfloat16 sm[];

    const int tid = threadIdx.x;
    const int wid = tid >> 5;
    const int lane = tid & 31;
    const int bm = blockIdx.y * 128;
    const int bn = blockIdx.x * 128;
    const int wm = (wid >> 1) * 32;
    const int wn = (wid & 1) * 64;

    float acc[2][8][4];
#pragma unroll
    for (int mi = 0; mi < 2; mi++)
#pragma unroll
        for (int ni = 0; ni < 8; ni++)
#pragma unroll
            for (int j = 0; j < 4; j++) acc[mi][ni][j] = 0.f;

    auto stage = [&](int k0, int st) {
        __nv_bfloat16* sA = sm + st * 2 * STG_ELE;
        __nv_bfloat16* sB = sA + STG_ELE;
#pragma unroll
        for (int i = 0; i < 2; i++) {
            int id = tid + i * 256;             // 0..511
            int r = id >> 2, c = (id & 3) * 8;  // 4 chunks of 8 units per row
            cp_async16(smem_u32(sA + r * SPAD + c), A + (size_t)(bm + r) * K + k0 + c);
            cp_async16(smem_u32(sB + r * SPAD + c), B + (size_t)(bn + r) * K + k0 + c);
        }
        cp_commit();
    };

    const int NS = K / BK;    // 64
    stage(0, 0);
    stage(BK, 1);

    for (int s = 0; s < NS; s++) {
        cp_wait<1>();                          // stage s complete
        __syncthreads();
        const int st = s % 3;
        if (s + 2 < NS) stage((s + 2) * BK, (s + 2) % 3);

        const __nv_bfloat16* sA = sm + st * 2 * STG_ELE;
        const __nv_bfloat16* sB = sA + STG_ELE;
#pragma unroll
        for (int ks = 0; ks < 2; ks++) {
            uint32_t af[2][4];
#pragma unroll
            for (int mi = 0; mi < 2; mi++)
                ldm_x4(af[mi], smem_u32(sA + (wm + mi * 16 + (lane & 15)) * SPAD
                                           + ks * 16 + (lane >> 4) * 8));
            uint32_t bf[4][4];
#pragma unroll
            for (int np = 0; np < 4; np++) {
                int rrow = wn + np * 16 + (lane & 7) + ((lane >> 4) << 3);
                int rcol = ks * 16 + (((lane >> 3) & 1) << 3);
                ldm_x4(bf[np], smem_u32(sB + rrow * SPAD + rcol));
            }
#pragma unroll
            for (int mi = 0; mi < 2; mi++)
#pragma unroll
                for (int ni = 0; ni < 8; ni++)
                    mma_bf16(acc[mi][ni], af[mi], &bf[ni >> 1][(ni & 1) * 2]);
        }
    }
    __syncthreads();

    const int gr = lane >> 2;         // 0..7
    const int gc = (lane & 3) * 2;    // 0,2,4,6

    if (EPI == 0) {
#pragma unroll
        for (int mi = 0; mi < 2; mi++) {
#pragma unroll
            for (int ni = 0; ni < 8; ni++) {
                int col = bn + wn + ni * 8 + gc;
                int row0 = bm + wm + mi * 16 + gr;
                __nv_bfloat162 lo = __floats2bfloat162_rn(acc[mi][ni][0], acc[mi][ni][1]);
                __nv_bfloat162 hi = __floats2bfloat162_rn(acc[mi][ni][2], acc[mi][ni][3]);
                *(__nv_bfloat162*)&Cv[(size_t)row0 * N + col] = lo;
                *(__nv_bfloat162*)&Cv[(size_t)(row0 + 8) * N + col] = hi;
            }
        }
    } else {
        // smem: W_out tile [128][5], bias tile [128], cross-warp accum [128][5]
        float* sW = (float*)sm;
        float* sbp = sW + 128 * A_DIM;
        float* sAcc = sbp + 128;
        for (int i = tid; i < 128 * A_DIM; i += 256) {
            int c = i / A_DIM, a = i % A_DIM;
            sW[i] = Wout[(size_t)(bn + c) * A_DIM + a];
        }
        for (int i = tid; i < 128; i += 256) sbp[i] = bias[bn + i];
        __syncthreads();

        // each warp: 32 rows (wm..wm+31), LIF + multiply by W_out slice, reduce quad
        float pr[2][2][A_DIM];
#pragma unroll
        for (int mi = 0; mi < 2; mi++) {
#pragma unroll
            for (int h = 0; h < 2; h++) {
                float p[A_DIM];
#pragma unroll
                for (int a = 0; a < A_DIM; a++) p[a] = 0.f;
#pragma unroll
                for (int ni = 0; ni < 8; ni++) {
                    int cl = wn + ni * 8 + gc;
                    float v0 = lif_rate(acc[mi][ni][2 * h + 0] + sbp[cl]);
                    float v1 = lif_rate(acc[mi][ni][2 * h + 1] + sbp[cl + 1]);
#pragma unroll
                    for (int a = 0; a < A_DIM; a++)
                        p[a] = fmaf(v0, sW[cl * A_DIM + a],
                                    fmaf(v1, sW[(cl + 1) * A_DIM + a], p[a]));
                }
#pragma unroll
                for (int a = 0; a < A_DIM; a++) {
                    p[a] += __shfl_xor_sync(0xffffffffu, p[a], 1);
                    p[a] += __shfl_xor_sync(0xffffffffu, p[a], 2);
                    pr[mi][h][a] = p[a];
                }
            }
        }
        // wn=64 warps deposit, wn=0 warps combine and store (deterministic)
        if (wn == 64 && (lane & 3) == 0) {
#pragma unroll
            for (int mi = 0; mi < 2; mi++)
#pragma unroll
                for (int h = 0; h < 2; h++) {
                    int rl = wm + mi * 16 + h * 8 + gr;
#pragma unroll
                    for (int a = 0; a < A_DIM; a++) sAcc[rl * A_DIM + a] = pr[mi][h][a];
                }
        }
        __syncthreads();
        if (wn == 0 && (lane & 3) == 0) {
#pragma unroll
            for (int mi = 0; mi < 2; mi++)
#pragma unroll
                for (int h = 0; h < 2; h++) {
                    int rl = wm + mi * 16 + h * 8 + gr;
#pragma unroll
                    for (int a = 0; a < A_DIM; a++)
                        pre_part[(size_t)blockIdx.x * (B_DIM * A_DIM)
                                 + (size_t)(bm + rl) * A_DIM + a] =
                            pr[mi][h][a] + sAcc[rl * A_DIM + a];
                }
        }
    }
}

// ---------------- conversion kernels ----------------
__global__ void conv_bf16_kernel(const float4* __restrict__ in, uint2* __restrict__ out, int n4) {
    int i = blockIdx.x * 256 + threadIdx.x;
    if (i < n4) {
        float4 v = in[i];
        __nv_bfloat162 lo = __floats2bfloat162_rn(v.x, v.y);
        __nv_bfloat162 hi = __floats2bfloat162_rn(v.z, v.w);
        uint2 o;
        o.x = *reinterpret_cast<unsigned int*>(&lo);
        o.y = *reinterpret_cast<unsigned int*>(&hi);
        out[i] = o;
    }
}

// out[j,m] = bf16(in[m,j]); also bias partials g_bp_part[m-blk][j]
__global__ void convT_bf16_bias_kernel(const float* __restrict__ in,
                                       const float* __restrict__ b_in,
                                       __nv_bfloat16* __restrict__ out) {
    __shared__ float t[32][33];
    int j0 = blockIdx.x * 32, m0 = blockIdx.y * 32;
    int tx = threadIdx.x, ty = threadIdx.y;   // 32 x 8
#pragma unroll
    for (int i = 0; i < 4; i++)
        t[ty + i * 8][tx] = in[(size_t)(m0 + ty + i * 8) * H_DIM + j0 + tx];
    __syncthreads();
#pragma unroll
    for (int i = 0; i < 4; i++)
        out[(size_t)(j0 + ty + i * 8) * H_DIM + m0 + tx] = __float2bfloat16(t[tx][ty + i * 8]);
    if (ty == 0) {
        float acc = 0.f;
#pragma unroll 8
        for (int mi = 0; mi < 32; mi++)
            acc = fmaf(b_in[m0 + mi], t[mi][tx], acc);
        g_bp_part[blockIdx.y][j0 + tx] = acc;
    }
}

// 64 blocks; block handles 32 j's; 8-way split over 64 partials + smem reduce
__global__ void bp_reduce_kernel(const float* __restrict__ b_snn) {
    __shared__ float sm[8][33];
    int jl = threadIdx.x & 31, p = threadIdx.x >> 5;   // 256 threads: 32j x 8p
    int j = blockIdx.x * 32 + jl;
    float acc = 0.f;
#pragma unroll
    for (int i = 0; i < 8; i++) acc += g_bp_part[p + 8 * i][j];
    sm[p][jl] = acc;
    __syncthreads();
    if (p == 0) {
        float r = b_snn[j];
#pragma unroll
        for (int i = 0; i < 8; i++) r += sm[i][jl];
        g_bp[j] = r;
    }
}

// ---------------- head finish: sum 16 partials, add b_out, threshold ----------------
__global__ void head_finish_kernel(const float* __restrict__ pre_part,
                                   const float* __restrict__ b_out,
                                   float* __restrict__ out) {
    int i = blockIdx.x * 256 + threadIdx.x;
    if (i < B_DIM * A_DIM) {
        float acc = b_out[i % A_DIM];
#pragma unroll
        for (int nb = 0; nb < 16; nb++)
            acc += pre_part[(size_t)nb * (B_DIM * A_DIM) + i];
        float v = acc * 0.5f;
        out[i] = (v - 1.0f >= 0.f) ? 1.f : 0.f;
    }
}

// ---------------- launch ----------------
extern "C" void kernel_launch(void* const* d_in, const int* in_sizes, int n_in,
                              void* d_out, int out_size) {
    const float* x     = (const float*)d_in[0];
    const float* W_in  = (const float*)d_in[1];
    const float* b_in  = (const float*)d_in[2];
    const float* W_snn = (const float*)d_in[3];
    const float* b_snn = (const float*)d_in[4];
    const float* W_out = (const float*)d_in[5];
    const float* b_out = (const float*)d_in[6];
    float* out = (float*)d_out;

    __nv_bfloat16 *xb, *Winb, *WsnnT, *WcT;
    float *bp, *pre_part;
    cudaGetSymbolAddress((void**)&xb,       g_xb);
    cudaGetSymbolAddress((void**)&Winb,     g_Winb);
    cudaGetSymbolAddress((void**)&WsnnT,    g_WsnnT);
    cudaGetSymbolAddress((void**)&WcT,      g_WcT);
    cudaGetSymbolAddress((void**)&bp,       g_bp);
    cudaGetSymbolAddress((void**)&pre_part, g_pre_part);

    cudaFuncSetAttribute(gemm_mma<0>, cudaFuncAttributeMaxDynamicSharedMemorySize, GEMM_SMEM);
    cudaFuncSetAttribute(gemm_mma<1>, cudaFuncAttributeMaxDynamicSharedMemorySize, GEMM_SMEM);

    // (1) W_in -> bf16
    conv_bf16_kernel<<<(H_DIM * H_DIM / 4 + 255) / 256, 256>>>(
        (const float4*)W_in, (uint2*)Winb, H_DIM * H_DIM / 4);
    // (2) W_snn^T -> bf16 (+ bias partials)
    convT_bf16_bias_kernel<<<dim3(H_DIM / 32, H_DIM / 32), dim3(32, 8)>>>(W_snn, b_in, WsnnT);
    // (3) bp = b_in @ W_snn + b_snn
    bp_reduce_kernel<<<H_DIM / 32, 256>>>(b_snn);
    // (4) GEMM1: WcT[j,i] = sum_m WsnnT[j,m] * Winb[i,m]     <- profiled launch
    gemm_mma<0><<<dim3(H_DIM / 128, H_DIM / 128), 256, GEMM_SMEM>>>(
        WsnnT, Winb, WcT, nullptr, nullptr, nullptr, H_DIM, H_DIM);
    // (5) x -> bf16
    conv_bf16_kernel<<<(B_DIM * H_DIM / 4 + 255) / 256, 256>>>(
        (const float4*)x, (uint2*)xb, B_DIM * H_DIM / 4);
    // (6) GEMM2 fused LIF + head partials
    gemm_mma<1><<<dim3(H_DIM / 128, B_DIM / 128), 256, GEMM_SMEM>>>(
        xb, WcT, nullptr, bp, W_out, pre_part, H_DIM, H_DIM);
    // (7) finish head
    head_finish_kernel<<<(B_DIM * A_DIM + 255) / 256, 256>>>(pre_part, b_out, out);
}